// round 8
// baseline (speedup 1.0000x reference)
#include <cuda_runtime.h>
#include <cuda_bf16.h>
#include <cstdint>

#define N_NODES 50000
#define N_EDGES 800000
#define FEAT    64
#define CAP     128

__device__ int g_cnt[N_NODES];   // zeroed at module load; gather resets it each launch
__device__ int g_slot[(size_t)N_NODES * CAP];

// ---------------------------------------------------------------------------
// Pass 1: bucket build. One thread per 4 edges (int4 loads).
// ---------------------------------------------------------------------------
__global__ void build_buckets_kernel(const int4* __restrict__ es4,
                                     const int4* __restrict__ ed4,
                                     int*        __restrict__ cnt,
                                     int*        __restrict__ slot)
{
    int t = blockIdx.x * blockDim.x + threadIdx.x;
    if (t >= N_EDGES / 4) return;
    int4 s = __ldg(es4 + t);
    int4 d = __ldg(ed4 + t);
    int p;
    p = atomicAdd(cnt + d.x, 1); if (p < CAP) slot[(size_t)d.x * CAP + p] = s.x;
    p = atomicAdd(cnt + d.y, 1); if (p < CAP) slot[(size_t)d.y * CAP + p] = s.y;
    p = atomicAdd(cnt + d.z, 1); if (p < CAP) slot[(size_t)d.z * CAP + p] = s.z;
    p = atomicAdd(cnt + d.w, 1); if (p < CAP) slot[(size_t)d.w * CAP + p] = s.w;
}

// ---------------------------------------------------------------------------
// Pass 2 (fused): R3 gather structure — NO launch_bounds; ptxas needs ~38
// regs to keep the 8 float4 gathers of a batch simultaneously in flight
// (regs<=32 serializes them: R7 showed 25us -> 41us). 16 threads/node.
// ---------------------------------------------------------------------------
#define NODES_PER_BLOCK 16   // 256 threads; 50000/16 = 3125 exact blocks

__global__ void
gather_matmul_kernel(const float4* __restrict__ src4,
                     const float4* __restrict__ dst4,
                     int*          __restrict__ cnt,
                     const int*    __restrict__ slot,
                     float*        __restrict__ out)
{
    __shared__ float  S_sm[NODES_PER_BLOCK][68];   // padded rows
    __shared__ float4 D_sm[NODES_PER_BLOCK][18];

    int local = threadIdx.x >> 4;
    int c     = threadIdx.x & 15;
    int n     = blockIdx.x * NODES_PER_BLOCK + local;   // exact grid

    int k = __ldg(cnt + n);
    // Independent dst-row load issued up front; latency overlaps the gathers.
    float4 dr = __ldg(dst4 + (size_t)n * 16 + c);
    if (c == 0) cnt[n] = 0;                // reset for next graph replay
    if (k > CAP) k = CAP;
    const int4* sl4 = reinterpret_cast<const int4*>(slot + (size_t)n * CAP);

    float4 acc = make_float4(0.f, 0.f, 0.f, 0.f);

    int j = 0;
    // 8-wide unroll: 8 independent 256B row gathers in flight per group.
    for (; j + 8 <= k; j += 8) {
        int4 s0 = __ldg(sl4 + (j >> 2));
        int4 s1 = __ldg(sl4 + (j >> 2) + 1);
        float4 v0 = __ldg(src4 + (size_t)s0.x * 16 + c);
        float4 v1 = __ldg(src4 + (size_t)s0.y * 16 + c);
        float4 v2 = __ldg(src4 + (size_t)s0.z * 16 + c);
        float4 v3 = __ldg(src4 + (size_t)s0.w * 16 + c);
        float4 v4 = __ldg(src4 + (size_t)s1.x * 16 + c);
        float4 v5 = __ldg(src4 + (size_t)s1.y * 16 + c);
        float4 v6 = __ldg(src4 + (size_t)s1.z * 16 + c);
        float4 v7 = __ldg(src4 + (size_t)s1.w * 16 + c);
        acc.x += (v0.x + v1.x) + (v2.x + v3.x) + ((v4.x + v5.x) + (v6.x + v7.x));
        acc.y += (v0.y + v1.y) + (v2.y + v3.y) + ((v4.y + v5.y) + (v6.y + v7.y));
        acc.z += (v0.z + v1.z) + (v2.z + v3.z) + ((v4.z + v5.z) + (v6.z + v7.z));
        acc.w += (v0.w + v1.w) + (v2.w + v3.w) + ((v4.w + v5.w) + (v6.w + v7.w));
    }
    if (j + 4 <= k) {
        int4 s0 = __ldg(sl4 + (j >> 2));
        float4 v0 = __ldg(src4 + (size_t)s0.x * 16 + c);
        float4 v1 = __ldg(src4 + (size_t)s0.y * 16 + c);
        float4 v2 = __ldg(src4 + (size_t)s0.z * 16 + c);
        float4 v3 = __ldg(src4 + (size_t)s0.w * 16 + c);
        acc.x += (v0.x + v1.x) + (v2.x + v3.x);
        acc.y += (v0.y + v1.y) + (v2.y + v3.y);
        acc.z += (v0.z + v1.z) + (v2.z + v3.z);
        acc.w += (v0.w + v1.w) + (v2.w + v3.w);
        j += 4;
    }
    for (; j < k; ++j) {
        int s = __ldg(slot + (size_t)n * CAP + j);
        float4 v = __ldg(src4 + (size_t)s * 16 + c);
        acc.x += v.x; acc.y += v.y; acc.z += v.z; acc.w += v.w;
    }

    *reinterpret_cast<float4*>(&S_sm[local][c * 4]) = acc;
    D_sm[local][c] = dr;
    __syncthreads();

    {
        int i  = c >> 1;
        int jh = c & 1;
        float4 o = make_float4(0.f, 0.f, 0.f, 0.f);
        #pragma unroll
        for (int p = 0; p < 8; ++p) {
            float  a = S_sm[local][i * 8 + p];
            float4 b = D_sm[local][p * 2 + jh];
            o.x = fmaf(a, b.x, o.x);
            o.y = fmaf(a, b.y, o.y);
            o.z = fmaf(a, b.z, o.z);
            o.w = fmaf(a, b.w, o.w);
        }
        const float inv = 0.3535533905932737622f;   // 1/sqrt(8)
        o.x *= inv; o.y *= inv; o.z *= inv; o.w *= inv;
        reinterpret_cast<float4*>(out + (size_t)n * FEAT)[c] = o;
    }
}

extern "C" void kernel_launch(void* const* d_in, const int* in_sizes, int n_in,
                              void* d_out, int out_size)
{
    const float* src_feat = (const float*)d_in[0];
    const float* dst_feat = (const float*)d_in[1];
    const int*   edge_src = (const int*)d_in[2];
    const int*   edge_dst = (const int*)d_in[3];
    float*       out      = (float*)d_out;

    void* cnt_ptr  = nullptr;
    void* slot_ptr = nullptr;
    cudaGetSymbolAddress(&cnt_ptr, g_cnt);
    cudaGetSymbolAddress(&slot_ptr, g_slot);

    // No memset: g_cnt starts zeroed (module load) and gather_matmul_kernel
    // resets it every launch, keeping the invariant across graph replays.

    {
        int threads = 256;
        int work    = N_EDGES / 4;                 // 200000
        int blocks  = (work + threads - 1) / threads;
        build_buckets_kernel<<<blocks, threads>>>(
            reinterpret_cast<const int4*>(edge_src),
            reinterpret_cast<const int4*>(edge_dst),
            (int*)cnt_ptr, (int*)slot_ptr);
    }
    {
        int threads = NODES_PER_BLOCK * 16;        // 256
        int blocks  = N_NODES / NODES_PER_BLOCK;   // 3125 exact
        gather_matmul_kernel<<<blocks, threads>>>(
            reinterpret_cast<const float4*>(src_feat),
            reinterpret_cast<const float4*>(dst_feat),
            (int*)cnt_ptr, (const int*)slot_ptr, out);
    }
}

// round 9
// speedup vs baseline: 1.4571x; 1.4571x over previous
#include <cuda_runtime.h>
#include <cuda_bf16.h>
#include <cstdint>

#define N_NODES 50000
#define N_EDGES 800000
#define FEAT    64
#define CAP     128

__device__ int g_cnt[N_NODES];
__device__ int g_slot[(size_t)N_NODES * CAP];

// ---------------------------------------------------------------------------
// Pass 1: bucket build. One thread per 4 edges (int4 loads).  (unchanged R3)
// ---------------------------------------------------------------------------
__global__ void build_buckets_kernel(const int4* __restrict__ es4,
                                     const int4* __restrict__ ed4,
                                     int*        __restrict__ cnt,
                                     int*        __restrict__ slot)
{
    int t = blockIdx.x * blockDim.x + threadIdx.x;
    if (t >= N_EDGES / 4) return;
    int4 s = __ldg(es4 + t);
    int4 d = __ldg(ed4 + t);
    int p;
    p = atomicAdd(cnt + d.x, 1); if (p < CAP) slot[(size_t)d.x * CAP + p] = s.x;
    p = atomicAdd(cnt + d.y, 1); if (p < CAP) slot[(size_t)d.y * CAP + p] = s.y;
    p = atomicAdd(cnt + d.z, 1); if (p < CAP) slot[(size_t)d.z * CAP + p] = s.z;
    p = atomicAdd(cnt + d.w, 1); if (p < CAP) slot[(size_t)d.w * CAP + p] = s.w;
}

// ---------------------------------------------------------------------------
// Pass 2 (fused): R3 structure, with ONE change — each node's first 32 slot
// indices are staged into smem by a cooperative coalesced burst at block
// start, so the per-batch slot->gather L2 dependence (~250cyc x2 per node)
// leaves the critical path. Indices are then read via broadcast LDS.
// Degree>32 (P~2e-4) falls back to global slot reads.
// NO launch_bounds: ptxas needs ~38-40 regs to keep the 8 float4 gathers of
// a batch in flight (forcing 32 regs serialized them: R7 25us->41us).
// ---------------------------------------------------------------------------
#define NODES_PER_BLOCK 16   // 256 threads; 50000/16 = 3125 exact blocks

__global__ void
gather_matmul_kernel(const float4* __restrict__ src4,
                     const float4* __restrict__ dst4,
                     const int*    __restrict__ cnt,
                     const int*    __restrict__ slot,
                     float*        __restrict__ out)
{
    __shared__ float  S_sm[NODES_PER_BLOCK][68];     // padded rows
    __shared__ float4 D_sm[NODES_PER_BLOCK][18];
    __shared__ int    slot_sm[NODES_PER_BLOCK][33];  // 32 idx + pad (bank-conflict-free)

    int local = threadIdx.x >> 4;
    int c     = threadIdx.x & 15;
    int n     = blockIdx.x * NODES_PER_BLOCK + local;   // exact grid

    // Cooperative stage: first 32 slot indices of every node in the block,
    // one int2 per thread, fully coalesced (128B per node row). Entries
    // beyond cnt[n] are stale-but-valid ids and never accumulated.
    {
        int2 v = __ldg(reinterpret_cast<const int2*>(slot + (size_t)n * CAP) + c);
        slot_sm[local][c * 2]     = v.x;
        slot_sm[local][c * 2 + 1] = v.y;
    }
    __syncthreads();

    int k = __ldg(cnt + n);
    if (k > CAP) k = CAP;
    int kc = k < 32 ? k : 32;

    float4 acc = make_float4(0.f, 0.f, 0.f, 0.f);

    int j = 0;
    // 8-wide unroll: indices from smem (broadcast LDS), 8 independent 256B
    // row gathers in flight per group.
    for (; j + 8 <= kc; j += 8) {
        int s0 = slot_sm[local][j + 0];
        int s1 = slot_sm[local][j + 1];
        int s2 = slot_sm[local][j + 2];
        int s3 = slot_sm[local][j + 3];
        int s4 = slot_sm[local][j + 4];
        int s5 = slot_sm[local][j + 5];
        int s6 = slot_sm[local][j + 6];
        int s7 = slot_sm[local][j + 7];
        float4 v0 = __ldg(src4 + (size_t)s0 * 16 + c);
        float4 v1 = __ldg(src4 + (size_t)s1 * 16 + c);
        float4 v2 = __ldg(src4 + (size_t)s2 * 16 + c);
        float4 v3 = __ldg(src4 + (size_t)s3 * 16 + c);
        float4 v4 = __ldg(src4 + (size_t)s4 * 16 + c);
        float4 v5 = __ldg(src4 + (size_t)s5 * 16 + c);
        float4 v6 = __ldg(src4 + (size_t)s6 * 16 + c);
        float4 v7 = __ldg(src4 + (size_t)s7 * 16 + c);
        acc.x += (v0.x + v1.x) + (v2.x + v3.x) + ((v4.x + v5.x) + (v6.x + v7.x));
        acc.y += (v0.y + v1.y) + (v2.y + v3.y) + ((v4.y + v5.y) + (v6.y + v7.y));
        acc.z += (v0.z + v1.z) + (v2.z + v3.z) + ((v4.z + v5.z) + (v6.z + v7.z));
        acc.w += (v0.w + v1.w) + (v2.w + v3.w) + ((v4.w + v5.w) + (v6.w + v7.w));
    }
    if (j + 4 <= kc) {
        int s0 = slot_sm[local][j + 0];
        int s1 = slot_sm[local][j + 1];
        int s2 = slot_sm[local][j + 2];
        int s3 = slot_sm[local][j + 3];
        float4 v0 = __ldg(src4 + (size_t)s0 * 16 + c);
        float4 v1 = __ldg(src4 + (size_t)s1 * 16 + c);
        float4 v2 = __ldg(src4 + (size_t)s2 * 16 + c);
        float4 v3 = __ldg(src4 + (size_t)s3 * 16 + c);
        acc.x += (v0.x + v1.x) + (v2.x + v3.x);
        acc.y += (v0.y + v1.y) + (v2.y + v3.y);
        acc.z += (v0.z + v1.z) + (v2.z + v3.z);
        acc.w += (v0.w + v1.w) + (v2.w + v3.w);
        j += 4;
    }
    for (; j < kc; ++j) {
        int s = slot_sm[local][j];
        float4 v = __ldg(src4 + (size_t)s * 16 + c);
        acc.x += v.x; acc.y += v.y; acc.z += v.z; acc.w += v.w;
    }
    // Rare fallback: degree > 32 — original global-index loop.
    for (j = 32; j < k; ++j) {
        int s = __ldg(slot + (size_t)n * CAP + j);
        float4 v = __ldg(src4 + (size_t)s * 16 + c);
        acc.x += v.x; acc.y += v.y; acc.z += v.z; acc.w += v.w;
    }

    *reinterpret_cast<float4*>(&S_sm[local][c * 4]) = acc;
    D_sm[local][c] = __ldg(dst4 + (size_t)n * 16 + c);
    __syncthreads();

    {
        int i  = c >> 1;
        int jh = c & 1;
        float4 o = make_float4(0.f, 0.f, 0.f, 0.f);
        #pragma unroll
        for (int p = 0; p < 8; ++p) {
            float  a = S_sm[local][i * 8 + p];
            float4 b = D_sm[local][p * 2 + jh];
            o.x = fmaf(a, b.x, o.x);
            o.y = fmaf(a, b.y, o.y);
            o.z = fmaf(a, b.z, o.z);
            o.w = fmaf(a, b.w, o.w);
        }
        const float inv = 0.3535533905932737622f;   // 1/sqrt(8)
        o.x *= inv; o.y *= inv; o.z *= inv; o.w *= inv;
        reinterpret_cast<float4*>(out + (size_t)n * FEAT)[c] = o;
    }
}

extern "C" void kernel_launch(void* const* d_in, const int* in_sizes, int n_in,
                              void* d_out, int out_size)
{
    const float* src_feat = (const float*)d_in[0];
    const float* dst_feat = (const float*)d_in[1];
    const int*   edge_src = (const int*)d_in[2];
    const int*   edge_dst = (const int*)d_in[3];
    float*       out      = (float*)d_out;

    void* cnt_ptr  = nullptr;
    void* slot_ptr = nullptr;
    cudaGetSymbolAddress(&cnt_ptr, g_cnt);
    cudaGetSymbolAddress(&slot_ptr, g_slot);

    // Memset node restored (R3 config — removing it regressed in R6-R8).
    cudaMemsetAsync(cnt_ptr, 0, (size_t)N_NODES * sizeof(int), 0);

    {
        int threads = 256;
        int work    = N_EDGES / 4;                 // 200000
        int blocks  = (work + threads - 1) / threads;
        build_buckets_kernel<<<blocks, threads>>>(
            reinterpret_cast<const int4*>(edge_src),
            reinterpret_cast<const int4*>(edge_dst),
            (int*)cnt_ptr, (int*)slot_ptr);
    }
    {
        int threads = NODES_PER_BLOCK * 16;        // 256
        int blocks  = N_NODES / NODES_PER_BLOCK;   // 3125 exact
        gather_matmul_kernel<<<blocks, threads>>>(
            reinterpret_cast<const float4*>(src_feat),
            reinterpret_cast<const float4*>(dst_feat),
            (const int*)cnt_ptr, (const int*)slot_ptr, out);
    }
}

// round 10
// speedup vs baseline: 1.5231x; 1.0453x over previous
#include <cuda_runtime.h>
#include <cuda_bf16.h>
#include <cstdint>

#define N_NODES 50000
#define N_EDGES 800000
#define FEAT    64
#define CAP     128

__device__ int g_cnt[N_NODES];
__device__ int g_slot[(size_t)N_NODES * CAP];

// ---------------------------------------------------------------------------
// Pass 1: bucket build. One thread per 8 edges (2x int4 loads) -> 8
// independent atomic+store chains per thread for latency hiding.
// ---------------------------------------------------------------------------
__global__ void build_buckets_kernel(const int4* __restrict__ es4,
                                     const int4* __restrict__ ed4,
                                     int*        __restrict__ cnt,
                                     int*        __restrict__ slot)
{
    int t = blockIdx.x * blockDim.x + threadIdx.x;
    if (t >= N_EDGES / 8) return;
    int4 s0 = __ldg(es4 + 2 * t);
    int4 s1 = __ldg(es4 + 2 * t + 1);
    int4 d0 = __ldg(ed4 + 2 * t);
    int4 d1 = __ldg(ed4 + 2 * t + 1);
    int p;
    p = atomicAdd(cnt + d0.x, 1); if (p < CAP) slot[(size_t)d0.x * CAP + p] = s0.x;
    p = atomicAdd(cnt + d0.y, 1); if (p < CAP) slot[(size_t)d0.y * CAP + p] = s0.y;
    p = atomicAdd(cnt + d0.z, 1); if (p < CAP) slot[(size_t)d0.z * CAP + p] = s0.z;
    p = atomicAdd(cnt + d0.w, 1); if (p < CAP) slot[(size_t)d0.w * CAP + p] = s0.w;
    p = atomicAdd(cnt + d1.x, 1); if (p < CAP) slot[(size_t)d1.x * CAP + p] = s1.x;
    p = atomicAdd(cnt + d1.y, 1); if (p < CAP) slot[(size_t)d1.y * CAP + p] = s1.y;
    p = atomicAdd(cnt + d1.z, 1); if (p < CAP) slot[(size_t)d1.z * CAP + p] = s1.z;
    p = atomicAdd(cnt + d1.w, 1); if (p < CAP) slot[(size_t)d1.w * CAP + p] = s1.w;
}

// ---------------------------------------------------------------------------
// Pass 2 (fused): R9 structure, with warp-local synchronization. All smem
// traffic for node `local` stays within one 16-thread half-warp, so
// __syncwarp replaces __syncthreads — decoupling the block's 16 nodes from
// each other (block-wide barrier made every node wait for the block's max
// degree). NO launch_bounds: ptxas needs ~38 regs to keep the 8 float4
// gathers of a batch in flight (forcing 32 regs: R7 25us->41us).
// ---------------------------------------------------------------------------
#define NODES_PER_BLOCK 16   // 256 threads; 50000/16 = 3125 exact blocks

__global__ void
gather_matmul_kernel(const float4* __restrict__ src4,
                     const float4* __restrict__ dst4,
                     const int*    __restrict__ cnt,
                     const int*    __restrict__ slot,
                     float*        __restrict__ out)
{
    __shared__ float  S_sm[NODES_PER_BLOCK][68];     // padded rows
    __shared__ float4 D_sm[NODES_PER_BLOCK][18];
    __shared__ int    slot_sm[NODES_PER_BLOCK][33];  // 32 idx + pad

    int local = threadIdx.x >> 4;
    int c     = threadIdx.x & 15;
    int n     = blockIdx.x * NODES_PER_BLOCK + local;   // exact grid

    // cnt load issued first — overlaps the staging load below.
    int k = __ldg(cnt + n);

    // Stage first 32 slot indices of this node (one int2/thread, coalesced).
    // Entries beyond cnt[n] are stale-but-valid ids, never accumulated.
    {
        int2 v = __ldg(reinterpret_cast<const int2*>(slot + (size_t)n * CAP) + c);
        slot_sm[local][c * 2]     = v.x;
        slot_sm[local][c * 2 + 1] = v.y;
    }
    __syncwarp();   // producers == consumers' half-warp; warp sync suffices

    if (k > CAP) k = CAP;
    int kc = k < 32 ? k : 32;

    float4 acc = make_float4(0.f, 0.f, 0.f, 0.f);

    int j = 0;
    // 8-wide unroll: indices from smem (broadcast LDS), 8 independent 256B
    // row gathers in flight per group.
    for (; j + 8 <= kc; j += 8) {
        int s0 = slot_sm[local][j + 0];
        int s1 = slot_sm[local][j + 1];
        int s2 = slot_sm[local][j + 2];
        int s3 = slot_sm[local][j + 3];
        int s4 = slot_sm[local][j + 4];
        int s5 = slot_sm[local][j + 5];
        int s6 = slot_sm[local][j + 6];
        int s7 = slot_sm[local][j + 7];
        float4 v0 = __ldg(src4 + (size_t)s0 * 16 + c);
        float4 v1 = __ldg(src4 + (size_t)s1 * 16 + c);
        float4 v2 = __ldg(src4 + (size_t)s2 * 16 + c);
        float4 v3 = __ldg(src4 + (size_t)s3 * 16 + c);
        float4 v4 = __ldg(src4 + (size_t)s4 * 16 + c);
        float4 v5 = __ldg(src4 + (size_t)s5 * 16 + c);
        float4 v6 = __ldg(src4 + (size_t)s6 * 16 + c);
        float4 v7 = __ldg(src4 + (size_t)s7 * 16 + c);
        acc.x += (v0.x + v1.x) + (v2.x + v3.x) + ((v4.x + v5.x) + (v6.x + v7.x));
        acc.y += (v0.y + v1.y) + (v2.y + v3.y) + ((v4.y + v5.y) + (v6.y + v7.y));
        acc.z += (v0.z + v1.z) + (v2.z + v3.z) + ((v4.z + v5.z) + (v6.z + v7.z));
        acc.w += (v0.w + v1.w) + (v2.w + v3.w) + ((v4.w + v5.w) + (v6.w + v7.w));
    }
    if (j + 4 <= kc) {
        int s0 = slot_sm[local][j + 0];
        int s1 = slot_sm[local][j + 1];
        int s2 = slot_sm[local][j + 2];
        int s3 = slot_sm[local][j + 3];
        float4 v0 = __ldg(src4 + (size_t)s0 * 16 + c);
        float4 v1 = __ldg(src4 + (size_t)s1 * 16 + c);
        float4 v2 = __ldg(src4 + (size_t)s2 * 16 + c);
        float4 v3 = __ldg(src4 + (size_t)s3 * 16 + c);
        acc.x += (v0.x + v1.x) + (v2.x + v3.x);
        acc.y += (v0.y + v1.y) + (v2.y + v3.y);
        acc.z += (v0.z + v1.z) + (v2.z + v3.z);
        acc.w += (v0.w + v1.w) + (v2.w + v3.w);
        j += 4;
    }
    for (; j < kc; ++j) {
        int s = slot_sm[local][j];
        float4 v = __ldg(src4 + (size_t)s * 16 + c);
        acc.x += v.x; acc.y += v.y; acc.z += v.z; acc.w += v.w;
    }
    // Rare fallback: degree > 32 — global slot reads.
    for (j = 32; j < k; ++j) {
        int s = __ldg(slot + (size_t)n * CAP + j);
        float4 v = __ldg(src4 + (size_t)s * 16 + c);
        acc.x += v.x; acc.y += v.y; acc.z += v.z; acc.w += v.w;
    }

    *reinterpret_cast<float4*>(&S_sm[local][c * 4]) = acc;
    D_sm[local][c] = __ldg(dst4 + (size_t)n * 16 + c);
    __syncwarp();   // same half-warp produces and consumes S_sm/D_sm rows

    {
        int i  = c >> 1;
        int jh = c & 1;
        float4 o = make_float4(0.f, 0.f, 0.f, 0.f);
        #pragma unroll
        for (int p = 0; p < 8; ++p) {
            float  a = S_sm[local][i * 8 + p];
            float4 b = D_sm[local][p * 2 + jh];
            o.x = fmaf(a, b.x, o.x);
            o.y = fmaf(a, b.y, o.y);
            o.z = fmaf(a, b.z, o.z);
            o.w = fmaf(a, b.w, o.w);
        }
        const float inv = 0.3535533905932737622f;   // 1/sqrt(8)
        o.x *= inv; o.y *= inv; o.z *= inv; o.w *= inv;
        reinterpret_cast<float4*>(out + (size_t)n * FEAT)[c] = o;
    }
}

extern "C" void kernel_launch(void* const* d_in, const int* in_sizes, int n_in,
                              void* d_out, int out_size)
{
    const float* src_feat = (const float*)d_in[0];
    const float* dst_feat = (const float*)d_in[1];
    const int*   edge_src = (const int*)d_in[2];
    const int*   edge_dst = (const int*)d_in[3];
    float*       out      = (float*)d_out;

    void* cnt_ptr  = nullptr;
    void* slot_ptr = nullptr;
    cudaGetSymbolAddress(&cnt_ptr, g_cnt);
    cudaGetSymbolAddress(&slot_ptr, g_slot);

    cudaMemsetAsync(cnt_ptr, 0, (size_t)N_NODES * sizeof(int), 0);

    {
        int threads = 256;
        int work    = N_EDGES / 8;                 // 100000
        int blocks  = (work + threads - 1) / threads;
        build_buckets_kernel<<<blocks, threads>>>(
            reinterpret_cast<const int4*>(edge_src),
            reinterpret_cast<const int4*>(edge_dst),
            (int*)cnt_ptr, (int*)slot_ptr);
    }
    {
        int threads = NODES_PER_BLOCK * 16;        // 256
        int blocks  = N_NODES / NODES_PER_BLOCK;   // 3125 exact
        gather_matmul_kernel<<<blocks, threads>>>(
            reinterpret_cast<const float4*>(src_feat),
            reinterpret_cast<const float4*>(dst_feat),
            (const int*)cnt_ptr, (const int*)slot_ptr, out);
    }
}